// round 6
// baseline (speedup 1.0000x reference)
#include <cuda_runtime.h>
#include <math.h>

// YearOperatorRouter: per-sample routed 3x3 edge magnitude.
// kx = [[-p,0,p],[-q,0,q],[-p,0,p]], ky = kx^T; out = sqrt(gx^2+gy^2+eps)*s, zero pad.
//
// R6: smem-staged tile. Block = 256 threads handles a full-width 256x16 output
// tile. Cooperative coalesced float4 loads of 18 input rows into smem (ideal
// L1 wavefronts), then each thread computes a 4x4 patch from smem with a
// rolling 3-row register window + shared vertical sum/diff rows + rsqrt.

#define W 256
#define H 256
#define TROWS 16            // output rows per block
#define SROWS (TROWS + 2)   // input rows staged (with vertical halo)

__global__ __launch_bounds__(256, 6)
void year_router_kernel(const float* __restrict__ x,
                        const float* __restrict__ alpha,
                        const float* __restrict__ scale,
                        const int*   __restrict__ year,
                        float* __restrict__ out,
                        int C)
{
    __shared__ float tile[SROWS][W];

    const int bc  = blockIdx.z;
    const int y0  = blockIdx.y * TROWS;
    const int tid = threadIdx.y * 64 + threadIdx.x;   // blockDim = (64,4)

    const float* __restrict__ base = x + (size_t)bc * H * W;

    // ---- cooperative load: SROWS x 64 float4, fully coalesced ----
#pragma unroll
    for (int idx = tid; idx < SROWS * (W / 4); idx += 256) {
        const int r = idx >> 6;
        const int c = idx & 63;
        const int gr = y0 - 1 + r;
        float4 v = make_float4(0.f, 0.f, 0.f, 0.f);
        if ((unsigned)gr < (unsigned)H)
            v = __ldg(reinterpret_cast<const float4*>(base + (size_t)gr * W) + c);
        *reinterpret_cast<float4*>(&tile[r][c * 4]) = v;
    }

    // ---- per-sample operator params (uniform per z-block), while loads fly ----
    const int b  = bc / C;
    const int yr = __ldg(year + b);
    float p, q, eps, s;
    if (yr == 2019) {            // sobel
        p = 1.0f; q = 2.0f; eps = 1e-8f; s = 1.0f;
    } else if (yr == 2020) {     // scharr
        p = 3.0f; q = 10.0f; eps = 1e-8f; s = 1.0f;
    } else {                     // learnable: sigmoid mix, normalized by max|k| (= q term)
        float a  = 1.0f / (1.0f + expf(-__ldg(alpha)));
        float pm = 3.0f  - 2.0f * a;
        float qm = 10.0f - 8.0f * a;   // qm > pm > 0 for a in (0,1)
        p = pm / qm; q = 1.0f;
        eps = 1e-6f;
        s = 1.0f / (1.0f + expf(-__ldg(scale)));
    }

    __syncthreads();

    const int sx = threadIdx.x * 4;   // 0..252
    const int sy = threadIdx.y * 4;   // local first output row; uses smem rows sy..sy+5

    float* __restrict__ obase = out + (size_t)bc * H * W;

    // ---- rolling 3-row register window fed from smem ----
    float rows[3][6];
#pragma unroll
    for (int w0 = 0; w0 < 2; w0++) {
        const float* sr = tile[sy + w0];
        float4 m = *reinterpret_cast<const float4*>(sr + sx);
        rows[w0][0] = (sx > 0)     ? sr[sx - 1] : 0.0f;
        rows[w0][1] = m.x; rows[w0][2] = m.y; rows[w0][3] = m.z; rows[w0][4] = m.w;
        rows[w0][5] = (sx + 4 < W) ? sr[sx + 4] : 0.0f;
    }

#pragma unroll
    for (int i = 0; i < 4; i++) {
        {
            const float* sr = tile[sy + i + 2];
            float* rn = rows[(i + 2) % 3];
            float4 m = *reinterpret_cast<const float4*>(sr + sx);
            rn[0] = (sx > 0)     ? sr[sx - 1] : 0.0f;
            rn[1] = m.x; rn[2] = m.y; rn[3] = m.z; rn[4] = m.w;
            rn[5] = (sx + 4 < W) ? sr[sx + 4] : 0.0f;
        }
        const float* r0 = rows[(i + 0) % 3];   // y-1
        const float* r1 = rows[(i + 1) % 3];   // y
        const float* r2 = rows[(i + 2) % 3];   // y+1

        // shared vertical sum/diff rows
        float d[6], t[6];
#pragma unroll
        for (int j = 0; j < 6; j++) { d[j] = r2[j] - r0[j]; t[j] = r2[j] + r0[j]; }

        float o[4];
#pragma unroll
        for (int j = 0; j < 4; j++) {
            float gx = fmaf(q, r1[j + 2] - r1[j], p * (t[j + 2] - t[j]));
            float gy = fmaf(q, d[j + 1],          p * (d[j] + d[j + 2]));
            float g2 = fmaf(gx, gx, fmaf(gy, gy, eps));
            o[j] = g2 * __frsqrt_rn(g2) * s;   // sqrt(g2)*s, g2 >= eps > 0
        }
        *reinterpret_cast<float4*>(obase + (size_t)(y0 + sy + i) * W + sx) =
            make_float4(o[0], o[1], o[2], o[3]);
    }
}

extern "C" void kernel_launch(void* const* d_in, const int* in_sizes, int n_in,
                              void* d_out, int out_size)
{
    const float* x     = (const float*)d_in[0];   // [B, C, 256, 256] f32
    const float* alpha = (const float*)d_in[1];   // scalar f32
    const float* scale = (const float*)d_in[2];   // [1] f32
    const int*   year  = (const int*)d_in[3];     // [B] int32
    float* out = (float*)d_out;

    const int B  = in_sizes[3];
    const int BC = in_sizes[0] / (H * W);
    const int C  = BC / B;

    dim3 block(64, 4, 1);
    dim3 grid(1, H / TROWS, BC);   // (1, 16, 288) = 4608 blocks

    year_router_kernel<<<grid, block>>>(x, alpha, scale, year, out, C);
}

// round 7
// speedup vs baseline: 1.2320x; 1.2320x over previous
#include <cuda_runtime.h>
#include <math.h>

// YearOperatorRouter: per-sample routed 3x3 edge magnitude.
// kx = [[-p,0,p],[-q,0,q],[-p,0,p]], ky = kx^T; out = sqrt(gx^2+gy^2+eps)*s, zero pad.
//
// R7: R4 skeleton (4-px-wide register window, no smem, no shuffles) with
// instruction-count cuts: rsqrt magnitude, s folded into (p,q,eps), shared
// vertical sum/diff rows, 8 output rows per thread.

#define W 256
#define H 256
#define RPT 8   // output rows per thread

__device__ __forceinline__ void load_row6(const float* __restrict__ row, int x0, float r[6]) {
    // 6-wide window [x0-1 .. x0+4]; x0 is a multiple of 4 so the middle 4 are one float4.
    float4 m = __ldg(reinterpret_cast<const float4*>(row + x0));
    r[0] = (x0 > 0) ? __ldg(row + x0 - 1) : 0.0f;
    r[1] = m.x; r[2] = m.y; r[3] = m.z; r[4] = m.w;
    r[5] = (x0 + 4 < W) ? __ldg(row + x0 + 4) : 0.0f;
}

__device__ __forceinline__ void zero_row6(float r[6]) {
#pragma unroll
    for (int j = 0; j < 6; j++) r[j] = 0.0f;
}

__global__ __launch_bounds__(128)
void year_router_kernel(const float* __restrict__ x,
                        const float* __restrict__ alpha,
                        const float* __restrict__ scale,
                        const int*   __restrict__ year,
                        float* __restrict__ out,
                        int C)
{
    const int x0 = threadIdx.x * 4;                                 // 0..252 (blockDim.x = 64)
    const int y0 = (blockIdx.y * 2 + threadIdx.y) * RPT;            // 0..248 (blockDim.y = 2)
    const int bc = blockIdx.z;
    const int b  = bc / C;

    // ---- per-sample operator parameters (uniform per z-block) ----
    const int yr = __ldg(year + b);
    float p, q, eps;
    if (yr == 2019) {            // sobel
        p = 1.0f; q = 2.0f; eps = 1e-8f;
    } else if (yr == 2020) {     // scharr
        p = 3.0f; q = 10.0f; eps = 1e-8f;
    } else {                     // learnable: sigmoid mix, normalized by max|k| (= q term),
                                 // output scale s folded into p,q (linear) and eps (s^2)
        float a  = 1.0f / (1.0f + expf(-__ldg(alpha)));
        float pm = 3.0f  - 2.0f * a;
        float qm = 10.0f - 8.0f * a;            // qm > pm > 0 for a in (0,1) -> max|k| = qm
        float s  = 1.0f / (1.0f + expf(-__ldg(scale)));
        p = (pm / qm) * s;
        q = s;
        eps = 1e-6f * s * s;
    }

    const float* __restrict__ base  = x   + (size_t)bc * H * W;
    float*       __restrict__ obase = out + (size_t)bc * H * W;

    // ---- rolling 3-row register window ----
    float rows[3][6];
    if (y0 > 0) load_row6(base + (size_t)(y0 - 1) * W, x0, rows[0]);
    else        zero_row6(rows[0]);
    load_row6(base + (size_t)y0 * W, x0, rows[1]);

#pragma unroll
    for (int i = 0; i < RPT; i++) {
        const int yn = y0 + i + 1;
        float* rn = rows[(i + 2) % 3];
        if (yn < H) load_row6(base + (size_t)yn * W, x0, rn);
        else        zero_row6(rn);

        const float* r0 = rows[(i + 0) % 3];   // y-1
        const float* r1 = rows[(i + 1) % 3];   // y
        const float* r2 = rn;                  // y+1

        // shared vertical sum/diff rows
        float d[6], t[6];
#pragma unroll
        for (int j = 0; j < 6; j++) { d[j] = r2[j] - r0[j]; t[j] = r2[j] + r0[j]; }

        float o[4];
#pragma unroll
        for (int j = 0; j < 4; j++) {
            float gx = fmaf(q, r1[j + 2] - r1[j], p * (t[j + 2] - t[j]));
            float gy = fmaf(q, d[j + 1],          p * (d[j] + d[j + 2]));
            float g2 = fmaf(gx, gx, fmaf(gy, gy, eps));
            o[j] = g2 * __frsqrt_rn(g2);       // sqrt(g2), g2 >= eps > 0
        }
        *reinterpret_cast<float4*>(obase + (size_t)(y0 + i) * W + x0) =
            make_float4(o[0], o[1], o[2], o[3]);
    }
}

extern "C" void kernel_launch(void* const* d_in, const int* in_sizes, int n_in,
                              void* d_out, int out_size)
{
    const float* x     = (const float*)d_in[0];   // [B, C, 256, 256] f32
    const float* alpha = (const float*)d_in[1];   // scalar f32
    const float* scale = (const float*)d_in[2];   // [1] f32
    const int*   year  = (const int*)d_in[3];     // [B] int32
    float* out = (float*)d_out;

    const int B  = in_sizes[3];
    const int BC = in_sizes[0] / (H * W);
    const int C  = BC / B;

    dim3 block(64, 2, 1);                 // 128 threads: 64 x-tiles, 2 row-strips
    dim3 grid(1, H / (RPT * 2), BC);      // (1, 16, 288) = 4608 blocks

    year_router_kernel<<<grid, block>>>(x, alpha, scale, year, out, C);
}